// round 17
// baseline (speedup 1.0000x reference)
#include <cuda_runtime.h>
#include <cuda_bf16.h>
#include <cstdint>

#define BATCH 32
#define SEQ   512
#define DM    1024
#define NSAMP 1000
#define SPAD  1024
#define LDB   144                        // smem row stride bytes (128 + 16 pad)
#define STG_A (128*LDB)                  // 18432
#define STAGE ((128+256)*LDB)            // 55296
#define NIT   32                         // 4 nc * 8 kc (K-chunk = 128 bytes)
#define OFF_BIAS (2*STAGE)               // 110592 f32[1024]
#define OFF_SW   (OFF_BIAS + 4096)       // 114688 f32[1024]
#define OFF_SID  (OFF_SW   + 4096)       // 118784 i32[1024]
#define OFF_MM   (OFF_SID  + 4096)       // 122880 f32[4][128]
#define OFF_LL   (OFF_MM   + 2048)       // 124928
#define SMEM_REQ (OFF_LL   + 2048)       // 126976

// ---------------- scratch (device globals; allocation-free rule) ----------------
__device__ int8_t g_Xq[BATCH*SEQ*DM];
__device__ int8_t g_Wq[BATCH*SPAD*DM];
__device__ float  g_sxS[BATCH*SEQ];
__device__ float  g_swS[BATCH*SPAD];
__device__ float  g_biasAdj[BATCH*SPAD];
__device__ int    g_sid[BATCH*SPAD];
__device__ float  g_trueAdj[BATCH*SEQ];
__device__ float  g_sum   = 0.f;
__device__ int    g_count = 0;

__device__ __forceinline__ float log_q_f(int id){
    float f = (float)id;
    float p = (logf(f + 2.0f) - logf(f + 1.0f)) / 10.819798284210285f; // log(50001)
    float t = 1000.0f * log1pf(-p);
    return logf(-expm1f(t));
}
__device__ __forceinline__ float amax4(float4 v){
    return fmaxf(fmaxf(fabsf(v.x), fabsf(v.y)), fmaxf(fabsf(v.z), fabsf(v.w)));
}
__device__ __forceinline__ uint32_t quant4(float4 v, float inv){
    int q0 = __float2int_rn(v.x*inv), q1 = __float2int_rn(v.y*inv);
    int q2 = __float2int_rn(v.z*inv), q3 = __float2int_rn(v.w*inv);
    return (uint32_t)(q0 & 0xff) | ((uint32_t)(q1 & 0xff) << 8)
         | ((uint32_t)(q2 & 0xff) << 16) | ((uint32_t)(q3 & 0xff) << 24);
}

// ---------------- prelude: gather+quantize W rows  +  exact f32 true logits + X quantize ----------------
__global__ void k_prep(const float* __restrict__ X, const int* __restrict__ nexts,
                       const int* __restrict__ samp, const float* __restrict__ W,
                       const float* __restrict__ bias){
    int lane = threadIdx.x & 31;
    if (blockIdx.x < 4096){
        int warp = (blockIdx.x*blockDim.x + threadIdx.x) >> 5;
        int b = warp >> 10, s = warp & 1023;
        int id = (s < NSAMP) ? samp[b*NSAMP + s] : -1;
        int8_t* dst = g_Wq + (size_t)warp*DM;
        if (id >= 0){
            const float4* src = (const float4*)(W + (size_t)id*DM);
            float4 v[8]; float am = 0.f;
            #pragma unroll
            for (int j=0;j<8;j++){ v[j] = src[lane + j*32]; am = fmaxf(am, amax4(v[j])); }
            #pragma unroll
            for (int off=16; off>0; off>>=1) am = fmaxf(am, __shfl_xor_sync(0xffffffffu, am, off));
            float sw  = am * (1.0f/127.0f);
            float inv = (am > 0.f) ? (127.0f/am) : 0.f;
            #pragma unroll
            for (int j=0;j<8;j++) ((uint32_t*)dst)[lane + j*32] = quant4(v[j], inv);
            if (lane == 0){ g_biasAdj[warp] = bias[id] - log_q_f(id); g_sid[warp] = id; g_swS[warp] = sw; }
        } else {
            #pragma unroll
            for (int j=0;j<8;j++) ((uint32_t*)dst)[lane + j*32] = 0u;
            if (lane == 0){ g_biasAdj[warp] = -1.0e30f; g_sid[warp] = -1; g_swS[warp] = 0.f; }
        }
    } else {
        int g = (blockIdx.x - 4096)*8 + (threadIdx.x >> 5);
        int id = nexts[g];
        const float4* xr = (const float4*)(X + (size_t)g*DM);
        const float4* wr = (const float4*)(W + (size_t)id*DM);
        int8_t* xo = g_Xq + (size_t)g*DM;
        float4 a[8]; float acc = 0.f, am = 0.f;
        #pragma unroll
        for (int j=0;j<8;j++){
            a[j] = xr[lane + j*32];
            float4 w4 = wr[lane + j*32];
            acc += a[j].x*w4.x + a[j].y*w4.y + a[j].z*w4.z + a[j].w*w4.w;
            am = fmaxf(am, amax4(a[j]));
        }
        #pragma unroll
        for (int off=16; off>0; off>>=1){
            acc += __shfl_xor_sync(0xffffffffu, acc, off);
            am   = fmaxf(am, __shfl_xor_sync(0xffffffffu, am, off));
        }
        float sx  = am * (1.0f/127.0f);
        float inv = (am > 0.f) ? (127.0f/am) : 0.f;
        #pragma unroll
        for (int j=0;j<8;j++) ((uint32_t*)xo)[lane + j*32] = quant4(a[j], inv);
        if (lane == 0){ g_trueAdj[g] = acc + bias[id] - log_q_f(id); g_sxS[g] = sx; }
    }
}

// ---------------- main: s8 mma.sync GEMM, 64x64 warp tiles, fused online logsumexp ----------------
// grid 128 (4 CTAs/batch, M=128). 8 warps in 2(M)x4(N) grid of 64x64 tiles.
// N-chunk=256 (nc=0..3), K-chunk=128 bytes (kc=0..7), kk=0..3 of K=32, 2-stage cp.async.
__device__ __forceinline__ void issue_stage(uint32_t sbase, int it,
    const int8_t* Ag, const int8_t* Bb, int tid){
    if (it < NIT){
        int nc = it >> 3, kc = it & 7;
        uint32_t st = sbase + (uint32_t)(it & 1)*STAGE;
        const int8_t* gA = Ag + kc*128;
        #pragma unroll
        for (int i=0;i<4;i++){
            int idx = tid + i*256; int row = idx >> 3, c = idx & 7;
            asm volatile("cp.async.cg.shared.global [%0],[%1],16;"
                :: "r"(st + (uint32_t)(row*LDB + c*16)), "l"(gA + (size_t)row*DM + c*16));
        }
        const int8_t* gB = Bb + (size_t)(nc*256)*DM + kc*128;
        #pragma unroll
        for (int i=0;i<8;i++){
            int idx = tid + i*256; int row = idx >> 3, c = idx & 7;
            asm volatile("cp.async.cg.shared.global [%0],[%1],16;"
                :: "r"(st + (uint32_t)(STG_A + row*LDB + c*16)), "l"(gB + (size_t)row*DM + c*16));
        }
    }
    asm volatile("cp.async.commit_group;");
}

__global__ __launch_bounds__(256,1)
void k_main(const int* __restrict__ nexts, float* __restrict__ out){
    extern __shared__ char smraw[];
    char* p = smraw;
    const uint32_t sbase = (uint32_t)__cvta_generic_to_shared(p);
    float* sBias = (float*)(p + OFF_BIAS);
    float* sSw   = (float*)(p + OFF_SW);
    int*   sSid  = (int*)  (p + OFF_SID);
    float* sMM   = (float*)(p + OFF_MM);
    float* sLL   = (float*)(p + OFF_LL);

    int tid = threadIdx.x, warp = tid >> 5, lane = tid & 31;
    int cta = blockIdx.x, b = cta >> 2, row0 = (cta & 3) << 7;
    int m0 = (warp >> 2) * 64, n0 = (warp & 3) * 64;

    for (int i=tid; i<SPAD; i+=256){
        sBias[i] = g_biasAdj[b*SPAD+i];
        sSw[i]   = g_swS[b*SPAD+i];
        sSid[i]  = g_sid[b*SPAD+i];
    }

    const int8_t* Ag = g_Xq + (size_t)(b*SEQ + row0)*DM;
    const int8_t* Bb = g_Wq + (size_t)b*SPAD*DM;

    int tv[8]; float sxv[8];
    #pragma unroll
    for (int mi=0;mi<4;mi++)
    #pragma unroll
    for (int h=0;h<2;h++){
        int r = row0 + m0 + mi*16 + h*8 + (lane>>2);
        tv[mi*2+h]  = nexts[b*SEQ + r];
        sxv[mi*2+h] = g_sxS[b*SEQ + r];
    }
    float m[8], l[8];
    #pragma unroll
    for (int i=0;i<8;i++){ m[i] = -3.0e38f; l[i] = 0.f; }

    issue_stage(sbase, 0, Ag, Bb, tid);

    int acc[4][8][4];
    for (int it=0; it<NIT; ++it){
        int nc = it >> 3, kc = it & 7;
        asm volatile("cp.async.wait_group 0;");
        __syncthreads();
        issue_stage(sbase, it+1, Ag, Bb, tid);

        if (kc == 0){
            #pragma unroll
            for (int mi=0;mi<4;mi++)
            #pragma unroll
            for (int j=0;j<8;j++)
            #pragma unroll
            for (int k=0;k<4;k++) acc[mi][j][k] = 0;
        }

        char* st = p + (it & 1)*STAGE;
        const int8_t* A = (const int8_t*)st;
        const int8_t* B = (const int8_t*)(st + STG_A);

        #pragma unroll
        for (int kk=0; kk<4; kk++){
            uint32_t af[4][4];
            #pragma unroll
            for (int mi=0;mi<4;mi++){
                const int8_t* q = A + (m0 + mi*16 + (lane & 15))*LDB + kk*32 + (lane >> 4)*16;
                uint32_t sa = (uint32_t)__cvta_generic_to_shared(q);
                asm volatile("ldmatrix.sync.aligned.m8n8.x4.shared.b16 {%0,%1,%2,%3},[%4];"
                    : "=r"(af[mi][0]), "=r"(af[mi][1]), "=r"(af[mi][2]), "=r"(af[mi][3]) : "r"(sa));
            }
            uint32_t bf[8][2];
            #pragma unroll
            for (int j=0;j<8;j+=2){
                const int8_t* q = B + (n0 + j*8 + (lane & 7) + (lane >> 4)*8)*LDB
                                    + kk*32 + ((lane >> 3) & 1)*16;
                uint32_t sb = (uint32_t)__cvta_generic_to_shared(q);
                asm volatile("ldmatrix.sync.aligned.m8n8.x4.shared.b16 {%0,%1,%2,%3},[%4];"
                    : "=r"(bf[j][0]), "=r"(bf[j][1]), "=r"(bf[j+1][0]), "=r"(bf[j+1][1]) : "r"(sb));
            }
            #pragma unroll
            for (int mi=0;mi<4;mi++)
            #pragma unroll
            for (int j=0;j<8;j++){
                asm volatile("mma.sync.aligned.m16n8k32.row.col.s32.s8.s8.s32 "
                    "{%0,%1,%2,%3},{%4,%5,%6,%7},{%8,%9},{%0,%1,%2,%3};"
                    : "+r"(acc[mi][j][0]), "+r"(acc[mi][j][1]), "+r"(acc[mi][j][2]), "+r"(acc[mi][j][3])
                    : "r"(af[mi][0]), "r"(af[mi][1]), "r"(af[mi][2]), "r"(af[mi][3]),
                      "r"(bf[j][0]), "r"(bf[j][1]));
            }
        }

        if (kc == 7){
            int cb = nc*256 + n0 + (lane & 3)*2;
            float2 bi[8], sw[8]; int2 si[8];
            #pragma unroll
            for (int j=0;j<8;j++){
                bi[j] = *(const float2*)&sBias[cb + j*8];
                sw[j] = *(const float2*)&sSw [cb + j*8];
                si[j] = *(const int2*)  &sSid[cb + j*8];
            }
            #pragma unroll
            for (int mi=0;mi<4;mi++)
            #pragma unroll
            for (int h=0;h<2;h++){
                int ri = mi*2 + h;
                float vv[16]; float bm = -3.0e38f;
                #pragma unroll
                for (int j=0;j<8;j++){
                    float v0 = fmaf((float)acc[mi][j][2*h],   sxv[ri]*sw[j].x, bi[j].x);
                    float v1 = fmaf((float)acc[mi][j][2*h+1], sxv[ri]*sw[j].y, bi[j].y);
                    if (si[j].x == tv[ri]) v0 = -1.0e9f;
                    if (si[j].y == tv[ri]) v1 = -1.0e9f;
                    vv[2*j] = v0; vv[2*j+1] = v1;
                    bm = fmaxf(bm, fmaxf(v0, v1));
                }
                float nm = fmaxf(m[ri], bm);
                float s = l[ri] * __expf(m[ri] - nm);
                #pragma unroll
                for (int j=0;j<16;j++) s += __expf(vv[j] - nm);
                l[ri] = s; m[ri] = nm;
            }
        }
    }

    // merge across the 4 lanes of each quad (same rows, different cols)
    #pragma unroll
    for (int o=1; o<=2; o<<=1){
        #pragma unroll
        for (int i=0;i<8;i++){
            float om = __shfl_xor_sync(0xffffffffu, m[i], o);
            float ol = __shfl_xor_sync(0xffffffffu, l[i], o);
            float nm = fmaxf(m[i], om);
            l[i] = l[i]*__expf(m[i]-nm) + ol*__expf(om-nm);
            m[i] = nm;
        }
    }
    if ((lane & 3) == 0){
        #pragma unroll
        for (int mi=0;mi<4;mi++)
        #pragma unroll
        for (int h=0;h<2;h++){
            int row = m0 + mi*16 + h*8 + (lane>>2);
            sMM[(warp & 3)*128 + row] = m[mi*2+h];
            sLL[(warp & 3)*128 + row] = l[mi*2+h];
        }
    }
    __syncthreads();

    // per-row loss + deterministic in-CTA reduction, then cross-CTA atomic finish
    float loss = 0.f;
    if (tid < 128){
        float M0 = sMM[tid],     L0 = sLL[tid];
        float M1 = sMM[128+tid], L1 = sLL[128+tid];
        float M2 = sMM[256+tid], L2 = sLL[256+tid];
        float M3 = sMM[384+tid], L3 = sLL[384+tid];
        float nm = fmaxf(fmaxf(M0,M1), fmaxf(M2,M3));
        float L  = L0*__expf(M0-nm) + L1*__expf(M1-nm) + L2*__expf(M2-nm) + L3*__expf(M3-nm);
        float ta = g_trueAdj[b*SEQ + row0 + tid];
        float fm = fmaxf(nm, ta);
        float FL = L*__expf(nm-fm) + __expf(ta-fm);
        loss = logf(FL) + fm - ta;
    }
    __syncthreads();
    #pragma unroll
    for (int o=16; o>0; o>>=1) loss += __shfl_xor_sync(0xffffffffu, loss, o);
    if (tid < 128 && lane == 0) sLL[warp] = loss;
    __syncthreads();
    if (tid == 0){
        float ctasum = sLL[0] + sLL[1] + sLL[2] + sLL[3];
        atomicAdd(&g_sum, ctasum);
        __threadfence();
        int old = atomicAdd(&g_count, 1);
        if (old == gridDim.x - 1){
            float tot = atomicAdd(&g_sum, 0.0f);
            out[0] = 0.5f * tot / (float)(BATCH*SEQ);
            __threadfence();
            g_sum = 0.f;
            g_count = 0;
        }
    }
}

extern "C" void kernel_launch(void* const* d_in, const int* in_sizes, int n_in,
                              void* d_out, int out_size){
    const float* X     = (const float*)d_in[0];
    const int*   nexts = (const int*)  d_in[1];
    const int*   samp  = (const int*)  d_in[2];
    const float* W     = (const float*)d_in[3];
    const float* bias  = (const float*)d_in[4];
    float* out = (float*)d_out;

    cudaFuncSetAttribute(k_main, cudaFuncAttributeMaxDynamicSharedMemorySize, SMEM_REQ);

    k_prep <<<4096 + 2048, 256>>>(X, nexts, samp, W, bias);
    k_main <<<BATCH*4, 256, SMEM_REQ>>>(nexts, out);
}